// round 7
// baseline (speedup 1.0000x reference)
#include <cuda_runtime.h>
#include <cuda_bf16.h>
#include <cstddef>

// ============================================================================
// MiniQuixerPQCBlock — exact MPS (bond dim 16) contraction of the PQC.
//
// Circuit: RX-encode (angles = pi*tanh(ctx@W^T + b)), then 4 layers of
// [RX,RY,RZ per wire + sequential CNOT chain]. The CNOT chain is the
// prefix-XOR basis permutation, crossing every contiguous cut exactly once
// per layer -> exact Schmidt rank <= 16. We contract the resulting chain
// tensor network per batch in one CTA: left/right environment sweeps over
// 16 sites with 8x8 complex matrix sandwiches, then <Z_q> = signed dot of
// matched environments.
// ============================================================================

__device__ __forceinline__ float2 cmul(float2 a, float2 b) {
    return make_float2(a.x * b.x - a.y * b.y, a.x * b.y + a.y * b.x);
}
// a * conj(b)
__device__ __forceinline__ float2 cmulc(float2 a, float2 b) {
    return make_float2(a.x * b.x + a.y * b.y, a.y * b.x - a.x * b.y);
}
__device__ __forceinline__ float2 cadd(float2 a, float2 b) {
    return make_float2(a.x + b.x, a.y + b.y);
}

// Build site tensor K for site q into Kq. One entry per thread (256 entries).
// K[jn*2+j][b*8+a] = U4[jn^j, b3]*U3[b3^a3, b2]*U2[b2^a2, b1]*w[b1^a1]
#define BUILD_K(qq)                                                            \
    {                                                                          \
        int jnj = tid >> 6, jn_ = jnj >> 1, j_ = jnj & 1;                      \
        int rest = tid & 63, b_ = rest >> 3, a_ = rest & 7;                    \
        int b3 = (b_ >> 2) & 1, b2 = (b_ >> 1) & 1, b1 = b_ & 1;               \
        int a3 = (a_ >> 2) & 1, a2 = (a_ >> 1) & 1, a1 = a_ & 1;               \
        float2 v_ = cmul(cmul(Usm[3][qq][(((jn_ ^ j_) << 1) | b3)],            \
                              Usm[2][qq][(((b3 ^ a3) << 1) | b2)]),            \
                         cmul(Usm[1][qq][(((b2 ^ a2) << 1) | b1)],             \
                              wsm[qq][b1 ^ a1]));                              \
        Kq[jnj][rest] = v_;                                                    \
    }

__global__ __launch_bounds__(256) void pqc_mps_kernel(
    const float* __restrict__ ctx,   // [B, 256]
    const float* __restrict__ Wm,    // [16, 256]
    const float* __restrict__ bv,    // [16]
    const float* __restrict__ prm,   // [4, 16, 3]
    float* __restrict__ out)         // [B, 16]
{
    __shared__ float2 Lsm[17][2][64];   // left environments L_0..L_16
    __shared__ float2 Rsm[17][2][64];   // right environments R_1..R_16
    __shared__ float2 Kq[4][64];        // site tensor (rebuilt per site)
    __shared__ float2 Tb[4][64];        // intermediate
    __shared__ float2 Usm[4][16][4];    // fused 1q gates, [layer][wire][r*2+c]
    __shared__ float2 wsm[16][2];       // U1 * RX(angle)|0>
    __shared__ float  pf[16][16];       // partial-dot / Z-partial scratch

    const int tid = threadIdx.x;
    const int bat = blockIdx.x;

    // ---------- encoding angle partial dot products ----------
    {
        int q = tid >> 4, s = tid & 15;
        const float* cr = ctx + (size_t)bat * 256;
        const float* wr = Wm + (size_t)q * 256;
        float acc = 0.f;
        #pragma unroll
        for (int k = 0; k < 16; ++k) acc += cr[s + 16 * k] * wr[s + 16 * k];
        pf[q][s] = acc;
    }

    // ---------- fused variational gates U = RZ(g)*RY(b)*RX(a) ----------
    if (tid < 64) {
        int l = tid >> 4, q = tid & 15;
        const float* p = prm + (size_t)(l * 16 + q) * 3;
        float ca = cosf(0.5f * p[0]), sa = sinf(0.5f * p[0]);
        float cb = cosf(0.5f * p[1]), sb = sinf(0.5f * p[1]);
        float cg = cosf(0.5f * p[2]), sg = sinf(0.5f * p[2]);
        // RX = [[X00, X01],[X01, X00]] with X00=ca, X01=-i*sa
        float2 X00 = make_float2(ca, 0.f), X01 = make_float2(0.f, -sa);
        // M = RY * RX, RY = [[cb,-sb],[sb,cb]] (real)
        float2 M00 = make_float2(cb * X00.x - sb * X01.x, cb * X00.y - sb * X01.y);
        float2 M01 = make_float2(cb * X01.x - sb * X00.x, cb * X01.y - sb * X00.y);
        float2 M10 = make_float2(sb * X00.x + cb * X01.x, sb * X00.y + cb * X01.y);
        float2 M11 = make_float2(sb * X01.x + cb * X00.x, sb * X01.y + cb * X00.y);
        float2 em = make_float2(cg, -sg), ep = make_float2(cg, sg);
        Usm[l][q][0] = cmul(em, M00);
        Usm[l][q][1] = cmul(em, M01);
        Usm[l][q][2] = cmul(ep, M10);
        Usm[l][q][3] = cmul(ep, M11);
    }
    __syncthreads();

    // ---------- angles -> encoding vector, fold layer-1 gate: w = U1 * v ----
    if (tid < 16) {
        float s = 0.f;
        #pragma unroll
        for (int k = 0; k < 16; ++k) s += pf[tid][k];
        float ang = 3.14159265358979323846f * tanhf(s + bv[tid]);
        float h = 0.5f * ang;
        float2 v0 = make_float2(cosf(h), 0.f);
        float2 v1 = make_float2(0.f, -sinf(h));
        wsm[tid][0] = cadd(cmul(Usm[0][tid][0], v0), cmul(Usm[0][tid][1], v1));
        wsm[tid][1] = cadd(cmul(Usm[0][tid][2], v0), cmul(Usm[0][tid][3], v1));
    }
    // boundary environments: L_0 = |0><0| on bond, R_16 = all-ones
    if (tid < 128) {
        int jn = tid >> 6, idx = tid & 63;
        Lsm[0][jn][idx]  = make_float2((jn == 0 && idx == 0) ? 1.f : 0.f, 0.f);
        Rsm[16][jn][idx] = make_float2(1.f, 0.f);
    }
    __syncthreads();

    // ---------- left sweep: L_{q+1}[jn] = sum_j K[jn,j] L_q[j] K[jn,j]^dag --
    for (int q = 0; q < 16; ++q) {
        BUILD_K(q);
        __syncthreads();
        // step 1: T[jnj][b][a'] = sum_a K[jnj][b][a] * L_q[j][a][a']
        {
            int jnj = tid >> 6, j = jnj & 1;
            int rest = tid & 63, b = rest >> 3, ap = rest & 7;
            float2 acc = make_float2(0.f, 0.f);
            #pragma unroll
            for (int a = 0; a < 8; ++a)
                acc = cadd(acc, cmul(Kq[jnj][(b << 3) | a], Lsm[q][j][(a << 3) | ap]));
            Tb[jnj][rest] = acc;
        }
        __syncthreads();
        // step 2: L_{q+1}[jn][b][b'] = sum_{j,a'} T[jnj][b][a'] * conj(K[jnj][b'][a'])
        if (tid < 128) {
            int jn = tid >> 6, rest = tid & 63, b = rest >> 3, bp = rest & 7;
            float2 acc = make_float2(0.f, 0.f);
            #pragma unroll
            for (int j = 0; j < 2; ++j)
                #pragma unroll
                for (int ap = 0; ap < 8; ++ap)
                    acc = cadd(acc, cmulc(Tb[(jn << 1) | j][(b << 3) | ap],
                                          Kq[(jn << 1) | j][(bp << 3) | ap]));
            Lsm[q + 1][jn][rest] = acc;
        }
        __syncthreads();
    }

    // ---------- right sweep: R_q[j] = sum_{jn} K^T R_{q+1}[jn] conj(K) -------
    for (int q = 15; q >= 1; --q) {
        BUILD_K(q);
        __syncthreads();
        // step 1: S[jnj][b][a'] = sum_{b'} R_{q+1}[jn][b][b'] * conj(K[jnj][b'][a'])
        {
            int jnj = tid >> 6, jn = jnj >> 1;
            int rest = tid & 63, b = rest >> 3, ap = rest & 7;
            float2 acc = make_float2(0.f, 0.f);
            #pragma unroll
            for (int bp = 0; bp < 8; ++bp)
                acc = cadd(acc, cmulc(Rsm[q + 1][jn][(b << 3) | bp],
                                      Kq[jnj][(bp << 3) | ap]));
            Tb[jnj][rest] = acc;
        }
        __syncthreads();
        // step 2: R_q[j][a][a'] = sum_{jn,b} K[jnj][b][a] * S[jnj][b][a']
        if (tid < 128) {
            int j = tid >> 6, rest = tid & 63, a = rest >> 3, ap = rest & 7;
            float2 acc = make_float2(0.f, 0.f);
            #pragma unroll
            for (int jn = 0; jn < 2; ++jn)
                #pragma unroll
                for (int b = 0; b < 8; ++b)
                    acc = cadd(acc, cmul(Kq[(jn << 1) | j][(b << 3) | a],
                                         Tb[(jn << 1) | j][(b << 3) | ap]));
            Rsm[q][j][rest] = acc;
        }
        __syncthreads();
    }

    // ---------- Z_q = sum_jn (-1)^jn  <L_{q+1}[jn], R_{q+1}[jn]> ------------
    {
        int q = tid >> 4, s = tid & 15;
        float acc = 0.f;
        #pragma unroll
        for (int k = 0; k < 8; ++k) {
            int idx = (s << 3) | k;           // 0..127
            int jn = idx >> 6, e = idx & 63;
            float2 l = Lsm[q + 1][jn][e];
            float2 r = Rsm[q + 1][jn][e];
            float re = l.x * r.x - l.y * r.y; // Re(l * r)
            acc += jn ? -re : re;
        }
        pf[q][s] = acc;
    }
    __syncthreads();
    if (tid < 16) {
        float z = 0.f;
        #pragma unroll
        for (int k = 0; k < 16; ++k) z += pf[tid][k];
        out[(size_t)bat * 16 + tid] = z;
    }
}

extern "C" void kernel_launch(void* const* d_in, const int* in_sizes, int n_in,
                              void* d_out, int out_size) {
    // Map inputs by element count (all four are distinct):
    // context [B,256], W [16,256]=4096, b [16], pqc_params [4,16,3]=192
    const float* ctx = nullptr;
    const float* Wm  = nullptr;
    const float* bv  = nullptr;
    const float* prm = nullptr;
    for (int i = 0; i < n_in; ++i) {
        int sz = in_sizes[i];
        const float* p = (const float*)d_in[i];
        if (sz == 16)        bv  = p;
        else if (sz == 192)  prm = p;
        else if (sz == 4096) Wm  = p;
        else                 ctx = p;  // B*256
    }
    // positional fallback if sizes ever collide
    if (!ctx) ctx = (const float*)d_in[0];
    if (!Wm)  Wm  = (const float*)d_in[1];
    if (!bv)  bv  = (const float*)d_in[2];
    if (!prm) prm = (const float*)d_in[3];

    float* out = (float*)d_out;
    int B = out_size / 16;
    if (B <= 0) return;
    pqc_mps_kernel<<<B, 256>>>(ctx, Wm, bv, prm, out);
}

// round 8
// speedup vs baseline: 1.3301x; 1.3301x over previous
#include <cuda_runtime.h>
#include <cuda_bf16.h>
#include <cstddef>

// ============================================================================
// MiniQuixerPQCBlock — exact MPS (bond dim 16) contraction, register-built
// site tensors (no Kq smem), conflict-free padded scratch layouts, Z fused
// into the right sweep (ping-pong R), shfl pair-reduction in step 2.
// ============================================================================

__device__ __forceinline__ float2 cmul(float2 a, float2 b) {
    return make_float2(fmaf(a.x, b.x, -a.y * b.y), fmaf(a.x, b.y, a.y * b.x));
}
// c += a*b
__device__ __forceinline__ float2 cfma(float2 a, float2 b, float2 c) {
    c.x = fmaf(a.x, b.x, fmaf(-a.y, b.y, c.x));
    c.y = fmaf(a.x, b.y, fmaf(a.y, b.x, c.y));
    return c;
}
// a*conj(b)
__device__ __forceinline__ float2 cmulc(float2 a, float2 b) {
    return make_float2(fmaf(a.x, b.x, a.y * b.y), fmaf(a.y, b.x, -a.x * b.y));
}
// c += a*conj(b)
__device__ __forceinline__ float2 cfmac(float2 a, float2 b, float2 c) {
    c.x = fmaf(a.x, b.x, fmaf(a.y, b.y, c.x));
    c.y = fmaf(a.y, b.x, fmaf(-a.x, b.y, c.y));
    return c;
}

__global__ __launch_bounds__(256) void pqc_mps_kernel(
    const float* __restrict__ ctx,   // [B, 256]
    const float* __restrict__ Wm,    // [16, 256]
    const float* __restrict__ bv,    // [16]
    const float* __restrict__ prm,   // [4, 16, 3]
    float* __restrict__ out)         // [B, 16]
{
    __shared__ float2 Lsm[17][2][64];   // left environments (kept for Z)
    __shared__ float2 Rb[2][2][72];     // right env ping-pong, row stride 9
    __shared__ float2 Ts[4 * 68];       // step-1 scratch, jnj stride 68
    __shared__ float2 Usm[4][16][4];    // fused 1q gates [layer][wire][r*2+c]
    __shared__ float2 wsm[16][2];       // U1 * RX(angle)|0>
    __shared__ float  pf[16][16];
    __shared__ float  zp[16][4];        // per-warp Z partials

    const int tid = threadIdx.x;
    const int bat = blockIdx.x;

    // ---------- encoding angle partial dot products ----------
    {
        int q = tid >> 4, s = tid & 15;
        const float* cr = ctx + (size_t)bat * 256;
        const float* wr = Wm + (size_t)q * 256;
        float acc = 0.f;
        #pragma unroll
        for (int k = 0; k < 16; ++k) acc = fmaf(cr[s + 16 * k], wr[s + 16 * k], acc);
        pf[q][s] = acc;
    }
    // ---------- fused variational gates U = RZ*RY*RX ----------
    if (tid < 64) {
        int l = tid >> 4, q = tid & 15;
        const float* p = prm + (size_t)(l * 16 + q) * 3;
        float ca = cosf(0.5f * p[0]), sa = sinf(0.5f * p[0]);
        float cb = cosf(0.5f * p[1]), sb = sinf(0.5f * p[1]);
        float cg = cosf(0.5f * p[2]), sg = sinf(0.5f * p[2]);
        float2 X00 = make_float2(ca, 0.f), X01 = make_float2(0.f, -sa);
        float2 M00 = make_float2(cb * X00.x - sb * X01.x, cb * X00.y - sb * X01.y);
        float2 M01 = make_float2(cb * X01.x - sb * X00.x, cb * X01.y - sb * X00.y);
        float2 M10 = make_float2(sb * X00.x + cb * X01.x, sb * X00.y + cb * X01.y);
        float2 M11 = make_float2(sb * X01.x + cb * X00.x, sb * X01.y + cb * X00.y);
        float2 em = make_float2(cg, -sg), ep = make_float2(cg, sg);
        Usm[l][q][0] = cmul(em, M00);
        Usm[l][q][1] = cmul(em, M01);
        Usm[l][q][2] = cmul(ep, M10);
        Usm[l][q][3] = cmul(ep, M11);
    }
    __syncthreads();

    // ---------- encoding vector folded with layer-1 gate ----------
    if (tid < 16) {
        float s = 0.f;
        #pragma unroll
        for (int k = 0; k < 16; ++k) s += pf[tid][k];
        float ang = 3.14159265358979323846f * tanhf(s + bv[tid]);
        float h = 0.5f * ang;
        float2 v0 = make_float2(cosf(h), 0.f);
        float2 v1 = make_float2(0.f, -sinf(h));
        wsm[tid][0] = cfma(Usm[0][tid][1], v1, cmul(Usm[0][tid][0], v0));
        wsm[tid][1] = cfma(Usm[0][tid][3], v1, cmul(Usm[0][tid][2], v0));
    }
    // boundaries: L_0 = |0><0|, R_16 = ones
    if (tid < 128) {
        int jn = tid >> 6, idx = tid & 63;
        Lsm[0][jn][idx] = make_float2((jn == 0 && idx == 0) ? 1.f : 0.f, 0.f);
    }
    if (tid < 144) {
        int jn = tid / 72, e = tid - jn * 72;
        Rb[0][jn][e] = make_float2(1.f, 0.f);
    }
    __syncthreads();

    // layout A (step 1 of both sweeps): tid = jnj<<6 | b<<3 | ap
    const int jnj1 = tid >> 6, jn1 = jnj1 >> 1, j1 = jnj1 & 1;
    const int b1i = (tid >> 3) & 7, ap1 = tid & 7;
    const int b13 = b1i >> 2, b12 = (b1i >> 1) & 1, b11 = b1i & 1;
    const int ax3 = ap1 >> 2, ax2 = (ap1 >> 1) & 1, ax1 = ap1 & 1;
    // layout B (step 2 left): tid = jn<<7 | b<<4 | bp<<1 | j
    const int jn2 = tid >> 7, b2i = (tid >> 4) & 7, bp2 = (tid >> 1) & 7, j2 = tid & 1;
    const int p3 = bp2 >> 2, p2 = (bp2 >> 1) & 1, p1 = bp2 & 1;
    // layout C (step 2 right): tid = j<<7 | a<<4 | ap<<1 | jn
    const int jC = tid >> 7, aC = (tid >> 4) & 7, apC = (tid >> 1) & 7, jnC = tid & 1;
    const int c3 = aC >> 2, c2 = (aC >> 1) & 1, c1 = aC & 1;

    // =================== LEFT SWEEP ===================
    #pragma unroll 1
    for (int q = 0; q < 16; ++q) {
        // step 1: T[jnj][b][ap] = sum_a K[jnj][b][a] * L[j][a][ap]
        {
            float2 U4v  = Usm[3][q][((jn1 ^ j1) << 1) | b13];
            float2 P0   = cmul(U4v, Usm[2][q][(b13 << 1) | b12]);
            float2 P1   = cmul(U4v, Usm[2][q][((b13 ^ 1) << 1) | b12]);
            float2 U2x0 = Usm[1][q][(b12 << 1) | b11];
            float2 U2x1 = Usm[1][q][((b12 ^ 1) << 1) | b11];
            float2 w0 = wsm[q][b11], w1 = wsm[q][b11 ^ 1];
            float2 hw00 = cmul(U2x0, w0), hw01 = cmul(U2x0, w1);
            float2 hw10 = cmul(U2x1, w0), hw11 = cmul(U2x1, w1);
            const float2* Lr = Lsm[q][j1];
            float2 m00 = cfma(hw01, Lr[ 8 + ap1], cmul(hw00, Lr[ 0 + ap1]));
            float2 m01 = cfma(hw11, Lr[24 + ap1], cmul(hw10, Lr[16 + ap1]));
            float2 m10 = cfma(hw01, Lr[40 + ap1], cmul(hw00, Lr[32 + ap1]));
            float2 m11 = cfma(hw11, Lr[56 + ap1], cmul(hw10, Lr[48 + ap1]));
            float2 n0 = make_float2(m00.x + m01.x, m00.y + m01.y);
            float2 n1 = make_float2(m10.x + m11.x, m10.y + m11.y);
            Ts[jnj1 * 68 + (b1i << 3) + ap1] = cfma(P1, n1, cmul(P0, n0));
        }
        __syncthreads();
        // step 2: L'[jn][b][bp] = sum_{j,ap} T[jnj][b][ap] * conj(K[jnj][bp][ap])
        {
            int jnj = (jn2 << 1) | j2;
            float2 U4v  = Usm[3][q][((jn2 ^ j2) << 1) | p3];
            float2 U3y0 = Usm[2][q][(p3 << 1) | p2];
            float2 U3y1 = Usm[2][q][((p3 ^ 1) << 1) | p2];
            float2 U2y0 = Usm[1][q][(p2 << 1) | p1];
            float2 U2y1 = Usm[1][q][((p2 ^ 1) << 1) | p1];
            float2 w0 = wsm[q][p1], w1 = wsm[q][p1 ^ 1];
            const float2* Tr = Ts + jnj * 68 + (b2i << 3);
            float2 m00 = cfmac(Tr[1], w1, cmulc(Tr[0], w0));
            float2 m01 = cfmac(Tr[3], w1, cmulc(Tr[2], w0));
            float2 m10 = cfmac(Tr[5], w1, cmulc(Tr[4], w0));
            float2 m11 = cfmac(Tr[7], w1, cmulc(Tr[6], w0));
            float2 n0 = cfmac(m01, U2y1, cmulc(m00, U2y0));
            float2 n1 = cfmac(m11, U2y1, cmulc(m10, U2y0));
            float2 t  = cfmac(n1, U3y1, cmulc(n0, U3y0));
            float2 part = cmulc(t, U4v);
            part.x += __shfl_xor_sync(0xffffffffu, part.x, 1);
            part.y += __shfl_xor_sync(0xffffffffu, part.y, 1);
            if (j2 == 0) Lsm[q + 1][jn2][(b2i << 3) | bp2] = part;
        }
        __syncthreads();
    }

    // =================== RIGHT SWEEP + fused Z ===================
    int cur = 0;
    #pragma unroll 1
    for (int q = 15; ; --q) {
        // Z_q = sum_jn (-1)^jn Re< L_{q+1}[jn], R_{q+1}[jn] >
        if (tid < 128) {
            int jn = tid >> 6, e = tid & 63;
            float2 l = Lsm[q + 1][jn][e];
            float2 r = Rb[cur][jn][(e >> 3) * 9 + (e & 7)];
            float term = l.x * r.x - l.y * r.y;
            term = jn ? -term : term;
            #pragma unroll
            for (int o = 16; o; o >>= 1)
                term += __shfl_xor_sync(0xffffffffu, term, o);
            if ((tid & 31) == 0) zp[q][tid >> 5] = term;
        }
        if (q == 0) break;
        // step 1: S[jnj][b][ap] = sum_bp R[jn][b][bp] * conj(K[jnj][bp][ap])
        {
            float2 w0 = wsm[q][ax1], w1 = wsm[q][ax1 ^ 1];
            float2 hw00 = cmul(Usm[1][q][(ax2 << 1) | 0], w0);
            float2 hw01 = cmul(Usm[1][q][(ax2 << 1) | 1], w1);
            float2 hw10 = cmul(Usm[1][q][((ax2 ^ 1) << 1) | 0], w0);
            float2 hw11 = cmul(Usm[1][q][((ax2 ^ 1) << 1) | 1], w1);
            const float2* Rr = Rb[cur][jn1] + b1i * 9;
            float2 m00 = cfmac(Rr[1], hw01, cmulc(Rr[0], hw00));
            float2 m01 = cfmac(Rr[3], hw11, cmulc(Rr[2], hw10));
            float2 m10 = cfmac(Rr[5], hw01, cmulc(Rr[4], hw00));
            float2 m11 = cfmac(Rr[7], hw11, cmulc(Rr[6], hw10));
            float2 n0 = cfmac(m01, Usm[2][q][(ax3 << 1) | 1],
                              cmulc(m00, Usm[2][q][(ax3 << 1) | 0]));
            float2 n1 = cfmac(m11, Usm[2][q][((ax3 ^ 1) << 1) | 1],
                              cmulc(m10, Usm[2][q][((ax3 ^ 1) << 1) | 0]));
            float2 acc = cfmac(n1, Usm[3][q][((jn1 ^ j1) << 1) | 1],
                               cmulc(n0, Usm[3][q][((jn1 ^ j1) << 1) | 0]));
            Ts[jnj1 * 68 + (b1i << 3) + ap1] = acc;
        }
        __syncthreads();
        // step 2: R'[j][a][ap] = sum_{jn,b} K[jnj][b][a] * S[jnj][b][ap]
        {
            int jnj = (jnC << 1) | jC;
            float2 w0 = wsm[q][c1], w1 = wsm[q][c1 ^ 1];
            float2 hw00 = cmul(Usm[1][q][(c2 << 1) | 0], w0);
            float2 hw01 = cmul(Usm[1][q][(c2 << 1) | 1], w1);
            float2 hw10 = cmul(Usm[1][q][((c2 ^ 1) << 1) | 0], w0);
            float2 hw11 = cmul(Usm[1][q][((c2 ^ 1) << 1) | 1], w1);
            const float2* Sr = Ts + jnj * 68;
            float2 m00 = cfma(hw01, Sr[ 8 + apC], cmul(hw00, Sr[ 0 + apC]));
            float2 m01 = cfma(hw11, Sr[24 + apC], cmul(hw10, Sr[16 + apC]));
            float2 m10 = cfma(hw01, Sr[40 + apC], cmul(hw00, Sr[32 + apC]));
            float2 m11 = cfma(hw11, Sr[56 + apC], cmul(hw10, Sr[48 + apC]));
            float2 n0 = cfma(Usm[2][q][(c3 << 1) | 1], m01,
                             cmul(Usm[2][q][(c3 << 1) | 0], m00));
            float2 n1 = cfma(Usm[2][q][((c3 ^ 1) << 1) | 1], m11,
                             cmul(Usm[2][q][((c3 ^ 1) << 1) | 0], m10));
            float2 part = cfma(Usm[3][q][((jnC ^ jC) << 1) | 1], n1,
                               cmul(Usm[3][q][((jnC ^ jC) << 1) | 0], n0));
            part.x += __shfl_xor_sync(0xffffffffu, part.x, 1);
            part.y += __shfl_xor_sync(0xffffffffu, part.y, 1);
            if (jnC == 0) Rb[cur ^ 1][jC][aC * 9 + apC] = part;
        }
        cur ^= 1;
        __syncthreads();
    }

    __syncthreads();
    if (tid < 16) {
        float z = zp[tid][0] + zp[tid][1] + zp[tid][2] + zp[tid][3];
        out[(size_t)bat * 16 + tid] = z;
    }
}

extern "C" void kernel_launch(void* const* d_in, const int* in_sizes, int n_in,
                              void* d_out, int out_size) {
    const float* ctx = nullptr;
    const float* Wm  = nullptr;
    const float* bv  = nullptr;
    const float* prm = nullptr;
    for (int i = 0; i < n_in; ++i) {
        int sz = in_sizes[i];
        const float* p = (const float*)d_in[i];
        if (sz == 16)        bv  = p;
        else if (sz == 192)  prm = p;
        else if (sz == 4096) Wm  = p;
        else                 ctx = p;  // B*256
    }
    if (!ctx) ctx = (const float*)d_in[0];
    if (!Wm)  Wm  = (const float*)d_in[1];
    if (!bv)  bv  = (const float*)d_in[2];
    if (!prm) prm = (const float*)d_in[3];

    float* out = (float*)d_out;
    int B = out_size / 16;
    if (B <= 0) return;
    pqc_mps_kernel<<<B, 256>>>(ctx, Wm, bv, prm, out);
}

// round 9
// speedup vs baseline: 1.5861x; 1.1925x over previous
#include <cuda_runtime.h>
#include <cuda_bf16.h>
#include <cstddef>

// ============================================================================
// MiniQuixerPQCBlock — exact MPS (bond dim 16) contraction.
// Warp-specialized: warps 0-3 left sweep, warps 4-7 right sweep, each with a
// private named barrier; Z computed in one final phase. float4 smem accesses.
// ============================================================================

__device__ __forceinline__ float2 cmul(float2 a, float2 b) {
    return make_float2(fmaf(a.x, b.x, -a.y * b.y), fmaf(a.x, b.y, a.y * b.x));
}
__device__ __forceinline__ float2 cfma(float2 a, float2 b, float2 c) {
    c.x = fmaf(a.x, b.x, fmaf(-a.y, b.y, c.x));
    c.y = fmaf(a.x, b.y, fmaf(a.y, b.x, c.y));
    return c;
}
__device__ __forceinline__ float2 cmulc(float2 a, float2 b) {  // a*conj(b)
    return make_float2(fmaf(a.x, b.x, a.y * b.y), fmaf(a.y, b.x, -a.x * b.y));
}
__device__ __forceinline__ float2 cfmac(float2 a, float2 b, float2 c) {  // c+=a*conj(b)
    c.x = fmaf(a.x, b.x, fmaf(a.y, b.y, c.x));
    c.y = fmaf(a.y, b.x, fmaf(-a.x, b.y, c.y));
    return c;
}
__device__ __forceinline__ float2 f2lo(float4 v) { return make_float2(v.x, v.y); }
__device__ __forceinline__ float2 f2hi(float4 v) { return make_float2(v.z, v.w); }

#define BARL asm volatile("bar.sync 1, 128;" ::: "memory")
#define BARR asm volatile("bar.sync 2, 128;" ::: "memory")

__global__ __launch_bounds__(256) void pqc_mps_kernel(
    const float* __restrict__ ctx,   // [B, 256]
    const float* __restrict__ Wm,    // [16, 256]
    const float* __restrict__ bv,    // [16]
    const float* __restrict__ prm,   // [4, 16, 3]
    float* __restrict__ out)         // [B, 16]
{
    __shared__ __align__(16) float2 Lsm[17][2][64];   // left envs L_0..L_16
    __shared__ __align__(16) float2 Rsm[17][2][64];   // right envs R_1..R_16 (+bnd)
    __shared__ __align__(16) float2 TsL[4][64];       // left-half scratch
    __shared__ __align__(16) float2 TsR[4][64];       // right-half scratch
    __shared__ float2 Usm[4][16][4];                  // fused gates [layer][wire][r*2+c]
    __shared__ float2 wsm[16][2];                     // U1 * RX(angle)|0>
    __shared__ float  pf[16][16];

    const int tid = threadIdx.x;
    const int bat = blockIdx.x;

    // ---------- encoding angle partial dots ----------
    {
        int q = tid >> 4, s = tid & 15;
        const float* cr = ctx + (size_t)bat * 256;
        const float* wr = Wm + (size_t)q * 256;
        float acc = 0.f;
        #pragma unroll
        for (int k = 0; k < 16; ++k) acc = fmaf(cr[s + 16 * k], wr[s + 16 * k], acc);
        pf[q][s] = acc;
    }
    // ---------- fused variational gates U = RZ*RY*RX ----------
    if (tid < 64) {
        int l = tid >> 4, q = tid & 15;
        const float* p = prm + (size_t)(l * 16 + q) * 3;
        float ca = cosf(0.5f * p[0]), sa = sinf(0.5f * p[0]);
        float cb = cosf(0.5f * p[1]), sb = sinf(0.5f * p[1]);
        float cg = cosf(0.5f * p[2]), sg = sinf(0.5f * p[2]);
        float2 X00 = make_float2(ca, 0.f), X01 = make_float2(0.f, -sa);
        float2 M00 = make_float2(cb * X00.x - sb * X01.x, cb * X00.y - sb * X01.y);
        float2 M01 = make_float2(cb * X01.x - sb * X00.x, cb * X01.y - sb * X00.y);
        float2 M10 = make_float2(sb * X00.x + cb * X01.x, sb * X00.y + cb * X01.y);
        float2 M11 = make_float2(sb * X01.x + cb * X00.x, sb * X01.y + cb * X00.y);
        float2 em = make_float2(cg, -sg), ep = make_float2(cg, sg);
        Usm[l][q][0] = cmul(em, M00);
        Usm[l][q][1] = cmul(em, M01);
        Usm[l][q][2] = cmul(ep, M10);
        Usm[l][q][3] = cmul(ep, M11);
    }
    // boundaries
    if (tid < 128) {
        Lsm[0][tid >> 6][tid & 63] = make_float2(tid == 0 ? 1.f : 0.f, 0.f);
    } else {
        int t = tid - 128;
        Rsm[16][t >> 6][t & 63] = make_float2(1.f, 0.f);
    }
    __syncthreads();

    // ---------- encoding vector folded with layer-1 gate ----------
    if (tid < 16) {
        float s = 0.f;
        #pragma unroll
        for (int k = 0; k < 16; ++k) s += pf[tid][k];
        float ang = 3.14159265358979323846f * tanhf(s + bv[tid]);
        float h = 0.5f * ang;
        float2 v0 = make_float2(cosf(h), 0.f);
        float2 v1 = make_float2(0.f, -sinf(h));
        wsm[tid][0] = cfma(Usm[0][tid][1], v1, cmul(Usm[0][tid][0], v0));
        wsm[tid][1] = cfma(Usm[0][tid][3], v1, cmul(Usm[0][tid][2], v0));
    }
    __syncthreads();

    if (tid < 128) {
        // =================== LEFT SWEEP (warps 0-3) ===================
        const int t = tid;
        // step1 layout: t = jnj<<5 | b<<2 | g   (thread does ap=2g, 2g+1)
        const int jnj = t >> 5, jn = jnj >> 1, j = jnj & 1;
        const int b = (t >> 2) & 7, g = t & 3;
        const int b3 = b >> 2, b2 = (b >> 1) & 1, b1 = b & 1;
        // step2 layout: t = jn2<<6 | b2i<<3 | bp2
        const int jn2 = t >> 6, b2i = (t >> 3) & 7, bp2 = t & 7;
        const int p3 = bp2 >> 2, p2 = (bp2 >> 1) & 1, p1 = bp2 & 1;

        #pragma unroll 1
        for (int q = 0; q < 16; ++q) {
            // step1: T[jnj][b][ap] = sum_a K[jnj][b][a] * L[j][a][ap]
            {
                float2 U4v  = Usm[3][q][((jn ^ j) << 1) | b3];
                float2 P0   = cmul(U4v, Usm[2][q][(b3 << 1) | b2]);
                float2 P1   = cmul(U4v, Usm[2][q][((b3 ^ 1) << 1) | b2]);
                float2 U2x0 = Usm[1][q][(b2 << 1) | b1];
                float2 U2x1 = Usm[1][q][((b2 ^ 1) << 1) | b1];
                float2 w0 = wsm[q][b1], w1 = wsm[q][b1 ^ 1];
                float2 hw00 = cmul(U2x0, w0), hw01 = cmul(U2x0, w1);
                float2 hw10 = cmul(U2x1, w0), hw11 = cmul(U2x1, w1);
                const float4* Lr = (const float4*)Lsm[q][j];  // idx = a*4 + g
                float4 A0 = Lr[0 + g],  A1 = Lr[4 + g],  A2 = Lr[8 + g],  A3 = Lr[12 + g];
                float4 A4 = Lr[16 + g], A5 = Lr[20 + g], A6 = Lr[24 + g], A7 = Lr[28 + g];
                float2 n0e = cfma(hw01, f2lo(A1), cmul(hw00, f2lo(A0)));
                n0e = cfma(hw10, f2lo(A2), n0e);  n0e = cfma(hw11, f2lo(A3), n0e);
                float2 n1e = cfma(hw01, f2lo(A5), cmul(hw00, f2lo(A4)));
                n1e = cfma(hw10, f2lo(A6), n1e);  n1e = cfma(hw11, f2lo(A7), n1e);
                float2 oe = cfma(P1, n1e, cmul(P0, n0e));
                float2 n0o = cfma(hw01, f2hi(A1), cmul(hw00, f2hi(A0)));
                n0o = cfma(hw10, f2hi(A2), n0o);  n0o = cfma(hw11, f2hi(A3), n0o);
                float2 n1o = cfma(hw01, f2hi(A5), cmul(hw00, f2hi(A4)));
                n1o = cfma(hw10, f2hi(A6), n1o);  n1o = cfma(hw11, f2hi(A7), n1o);
                float2 oo = cfma(P1, n1o, cmul(P0, n0o));
                ((float4*)(&TsL[jnj][b << 3]))[g] = make_float4(oe.x, oe.y, oo.x, oo.y);
            }
            BARL;
            // step2: L'[jn2][b2i][bp2] = sum_{j,ap} T[jnj][b2i][ap]*conj(K[jnj][bp2][ap])
            {
                float2 U3y0 = Usm[2][q][(p3 << 1) | p2];
                float2 U3y1 = Usm[2][q][((p3 ^ 1) << 1) | p2];
                float2 U2y0 = Usm[1][q][(p2 << 1) | p1];
                float2 U2y1 = Usm[1][q][((p2 ^ 1) << 1) | p1];
                float2 w0 = wsm[q][p1], w1 = wsm[q][p1 ^ 1];
                float2 acc = make_float2(0.f, 0.f);
                #pragma unroll
                for (int jj = 0; jj < 2; ++jj) {
                    const float4* Tr = (const float4*)(&TsL[(jn2 << 1) | jj][b2i << 3]);
                    float4 T0 = Tr[0], T1 = Tr[1], T2 = Tr[2], T3 = Tr[3];
                    float2 m00 = cfmac(f2hi(T0), w1, cmulc(f2lo(T0), w0));
                    float2 m01 = cfmac(f2hi(T1), w1, cmulc(f2lo(T1), w0));
                    float2 m10 = cfmac(f2hi(T2), w1, cmulc(f2lo(T2), w0));
                    float2 m11 = cfmac(f2hi(T3), w1, cmulc(f2lo(T3), w0));
                    float2 n0 = cfmac(m01, U2y1, cmulc(m00, U2y0));
                    float2 n1 = cfmac(m11, U2y1, cmulc(m10, U2y0));
                    float2 tt = cfmac(n1, U3y1, cmulc(n0, U3y0));
                    acc = cfmac(tt, Usm[3][q][((jn2 ^ jj) << 1) | p3], acc);
                }
                Lsm[q + 1][jn2][(b2i << 3) | bp2] = acc;
            }
            BARL;
        }
    } else {
        // =================== RIGHT SWEEP (warps 4-7) ===================
        const int t = tid - 128;
        const int jnj = t >> 5, jn = jnj >> 1, j = jnj & 1;
        const int b = (t >> 2) & 7, g = t & 3;
        const int x2 = g & 1, x3 = g >> 1;  // ap = 2g+e -> x1=e
        // step2 layout: t = jC<<6 | aC<<3 | apC
        const int jC = t >> 6, aC = (t >> 3) & 7, apC = t & 7;
        const int c3 = aC >> 2, c2 = (aC >> 1) & 1, c1 = aC & 1;

        #pragma unroll 1
        for (int q = 15; q >= 1; --q) {
            // step1: S[jnj][b][ap] = sum_bp R_{q+1}[jn][b][bp] * conj(K[jnj][bp][ap])
            {
                float2 U2a = Usm[1][q][(x2 << 1) | 0], U2b = Usm[1][q][(x2 << 1) | 1];
                float2 U2c = Usm[1][q][((x2 ^ 1) << 1) | 0], U2d = Usm[1][q][((x2 ^ 1) << 1) | 1];
                float2 wA = wsm[q][0], wB = wsm[q][1];
                // e=0 (x1=0)
                float2 h00 = cmul(U2a, wA), h01 = cmul(U2b, wB);
                float2 h10 = cmul(U2c, wA), h11 = cmul(U2d, wB);
                // e=1 (x1=1)
                float2 g00 = cmul(U2a, wB), g01 = cmul(U2b, wA);
                float2 g10 = cmul(U2c, wB), g11 = cmul(U2d, wA);
                float2 V30 = Usm[2][q][(x3 << 1) | 0], V31 = Usm[2][q][(x3 << 1) | 1];
                float2 V32 = Usm[2][q][((x3 ^ 1) << 1) | 0], V33 = Usm[2][q][((x3 ^ 1) << 1) | 1];
                float2 U40 = Usm[3][q][((jn ^ j) << 1) | 0];
                float2 U41 = Usm[3][q][((jn ^ j) << 1) | 1];
                const float4* Rr = (const float4*)(&Rsm[q + 1][jn][b << 3]);
                float4 R0 = Rr[0], R1 = Rr[1], R2 = Rr[2], R3 = Rr[3];
                // e=0
                float2 m00 = cfmac(f2hi(R0), h01, cmulc(f2lo(R0), h00));
                float2 m01 = cfmac(f2hi(R1), h11, cmulc(f2lo(R1), h10));
                float2 m10 = cfmac(f2hi(R2), h01, cmulc(f2lo(R2), h00));
                float2 m11 = cfmac(f2hi(R3), h11, cmulc(f2lo(R3), h10));
                float2 n0 = cfmac(m01, V31, cmulc(m00, V30));
                float2 n1 = cfmac(m11, V33, cmulc(m10, V32));
                float2 oe = cfmac(n1, U41, cmulc(n0, U40));
                // e=1
                m00 = cfmac(f2hi(R0), g01, cmulc(f2lo(R0), g00));
                m01 = cfmac(f2hi(R1), g11, cmulc(f2lo(R1), g10));
                m10 = cfmac(f2hi(R2), g01, cmulc(f2lo(R2), g00));
                m11 = cfmac(f2hi(R3), g11, cmulc(f2lo(R3), g10));
                n0 = cfmac(m01, V31, cmulc(m00, V30));
                n1 = cfmac(m11, V33, cmulc(m10, V32));
                float2 oo = cfmac(n1, U41, cmulc(n0, U40));
                ((float4*)(&TsR[jnj][b << 3]))[g] = make_float4(oe.x, oe.y, oo.x, oo.y);
            }
            BARR;
            // step2: R'[jC][aC][apC] = sum_{jn,b} K[jnj][b][aC] * S[jnj][b][apC]
            {
                float2 w0 = wsm[q][c1], w1 = wsm[q][c1 ^ 1];
                float2 hw00 = cmul(Usm[1][q][(c2 << 1) | 0], w0);
                float2 hw01 = cmul(Usm[1][q][(c2 << 1) | 1], w1);
                float2 hw10 = cmul(Usm[1][q][((c2 ^ 1) << 1) | 0], w0);
                float2 hw11 = cmul(Usm[1][q][((c2 ^ 1) << 1) | 1], w1);
                float2 V30 = Usm[2][q][(c3 << 1) | 0], V31 = Usm[2][q][(c3 << 1) | 1];
                float2 V32 = Usm[2][q][((c3 ^ 1) << 1) | 0], V33 = Usm[2][q][((c3 ^ 1) << 1) | 1];
                float2 acc = make_float2(0.f, 0.f);
                #pragma unroll
                for (int jnn = 0; jnn < 2; ++jnn) {
                    const float2* Sr = TsR[(jnn << 1) | jC];
                    float2 m00 = cfma(hw01, Sr[ 8 + apC], cmul(hw00, Sr[ 0 + apC]));
                    float2 m01 = cfma(hw11, Sr[24 + apC], cmul(hw10, Sr[16 + apC]));
                    float2 m10 = cfma(hw01, Sr[40 + apC], cmul(hw00, Sr[32 + apC]));
                    float2 m11 = cfma(hw11, Sr[56 + apC], cmul(hw10, Sr[48 + apC]));
                    float2 n0 = cfma(V31, m01, cmul(V30, m00));
                    float2 n1 = cfma(V33, m11, cmul(V32, m10));
                    float2 U40 = Usm[3][q][((jnn ^ jC) << 1) | 0];
                    float2 U41 = Usm[3][q][((jnn ^ jC) << 1) | 1];
                    acc = cfma(U40, n0, acc);
                    acc = cfma(U41, n1, acc);
                }
                Rsm[q][jC][(aC << 3) | apC] = acc;
            }
            BARR;
        }
    }

    __syncthreads();

    // ---------- Z_q = sum_jn (-1)^jn Re< L_{q+1}[jn], R_{q+1}[jn] > ----------
    {
        int q = tid >> 4, s = tid & 15;
        int jn = s >> 3, e8 = (s & 7) << 3;
        const float4* Lr = (const float4*)(&Lsm[q + 1][jn][e8]);
        const float4* Rr = (const float4*)(&Rsm[q + 1][jn][e8]);
        float acc = 0.f;
        #pragma unroll
        for (int c = 0; c < 4; ++c) {
            float4 l = Lr[c], r = Rr[c];
            acc += l.x * r.x - l.y * r.y + l.z * r.z - l.w * r.w;
        }
        if (jn) acc = -acc;
        #pragma unroll
        for (int o = 8; o; o >>= 1)
            acc += __shfl_xor_sync(0xffffffffu, acc, o);
        if (s == 0) out[(size_t)bat * 16 + q] = acc;
    }
}

extern "C" void kernel_launch(void* const* d_in, const int* in_sizes, int n_in,
                              void* d_out, int out_size) {
    const float* ctx = nullptr;
    const float* Wm  = nullptr;
    const float* bv  = nullptr;
    const float* prm = nullptr;
    for (int i = 0; i < n_in; ++i) {
        int sz = in_sizes[i];
        const float* p = (const float*)d_in[i];
        if (sz == 16)        bv  = p;
        else if (sz == 192)  prm = p;
        else if (sz == 4096) Wm  = p;
        else                 ctx = p;  // B*256
    }
    if (!ctx) ctx = (const float*)d_in[0];
    if (!Wm)  Wm  = (const float*)d_in[1];
    if (!bv)  bv  = (const float*)d_in[2];
    if (!prm) prm = (const float*)d_in[3];

    float* out = (float*)d_out;
    int B = out_size / 16;
    if (B <= 0) return;
    pqc_mps_kernel<<<B, 256>>>(ctx, Wm, bv, prm, out);
}

// round 10
// speedup vs baseline: 1.9207x; 1.2110x over previous
#include <cuda_runtime.h>
#include <cuda_bf16.h>
#include <cstddef>

// ============================================================================
// MiniQuixerPQCBlock — exact MPS (bond dim 16) contraction.
// Warp-specialized sweeps (warps 0-3 left, 4-7 right, named barriers).
// Step2 fused into step1 via shfl_xor butterfly reduce-scatter:
// one barrier per site, no intermediate smem scratch.
// ============================================================================

__device__ __forceinline__ float2 cmul(float2 a, float2 b) {
    return make_float2(fmaf(a.x, b.x, -a.y * b.y), fmaf(a.x, b.y, a.y * b.x));
}
__device__ __forceinline__ float2 cfma(float2 a, float2 b, float2 c) {
    c.x = fmaf(a.x, b.x, fmaf(-a.y, b.y, c.x));
    c.y = fmaf(a.x, b.y, fmaf(a.y, b.x, c.y));
    return c;
}
__device__ __forceinline__ float2 cmulc(float2 a, float2 b) {  // a*conj(b)
    return make_float2(fmaf(a.x, b.x, a.y * b.y), fmaf(a.y, b.x, -a.x * b.y));
}
__device__ __forceinline__ float2 cadd(float2 a, float2 b) {
    return make_float2(a.x + b.x, a.y + b.y);
}
__device__ __forceinline__ float2 f2lo(float4 v) { return make_float2(v.x, v.y); }
__device__ __forceinline__ float2 f2hi(float4 v) { return make_float2(v.z, v.w); }
__device__ __forceinline__ float2 shflx(float2 v, int m) {
    v.x = __shfl_xor_sync(0xffffffffu, v.x, m);
    v.y = __shfl_xor_sync(0xffffffffu, v.y, m);
    return v;
}

#define BARL asm volatile("bar.sync 1, 128;" ::: "memory")
#define BARR asm volatile("bar.sync 2, 128;" ::: "memory")

// L rows: [q][j][a*8+ap], j-stride 72 float2 (144 words ≡ 16 mod 32 -> no j conflicts)
// R rows: [q][jn][b*10+bp], b-stride 10 float2 (banks spread), jn-stride 80 float2

__global__ __launch_bounds__(256) void pqc_mps_kernel(
    const float* __restrict__ ctx,   // [B, 256]
    const float* __restrict__ Wm,    // [16, 256]
    const float* __restrict__ bv,    // [16]
    const float* __restrict__ prm,   // [4, 16, 3]
    float* __restrict__ out)         // [B, 16]
{
    __shared__ __align__(16) float2 Lsm[17][2][72];
    __shared__ __align__(16) float2 Rsm[17][2][80];
    __shared__ float2 Usm[4][16][4];   // fused gates [layer][wire][r*2+c]
    __shared__ float2 wsm[16][2];      // U1 * RX(angle)|0>
    __shared__ float  pf[16][16];

    const int tid = threadIdx.x;
    const int bat = blockIdx.x;

    // ---------- encoding angle partial dots ----------
    {
        int q = tid >> 4, s = tid & 15;
        const float* cr = ctx + (size_t)bat * 256;
        const float* wr = Wm + (size_t)q * 256;
        float acc = 0.f;
        #pragma unroll
        for (int k = 0; k < 16; ++k) acc = fmaf(cr[s + 16 * k], wr[s + 16 * k], acc);
        pf[q][s] = acc;
    }
    // ---------- fused variational gates U = RZ*RY*RX ----------
    if (tid < 64) {
        int l = tid >> 4, q = tid & 15;
        const float* p = prm + (size_t)(l * 16 + q) * 3;
        float ca = cosf(0.5f * p[0]), sa = sinf(0.5f * p[0]);
        float cb = cosf(0.5f * p[1]), sb = sinf(0.5f * p[1]);
        float cg = cosf(0.5f * p[2]), sg = sinf(0.5f * p[2]);
        float2 X00 = make_float2(ca, 0.f), X01 = make_float2(0.f, -sa);
        float2 M00 = make_float2(cb * X00.x - sb * X01.x, cb * X00.y - sb * X01.y);
        float2 M01 = make_float2(cb * X01.x - sb * X00.x, cb * X01.y - sb * X00.y);
        float2 M10 = make_float2(sb * X00.x + cb * X01.x, sb * X00.y + cb * X01.y);
        float2 M11 = make_float2(sb * X01.x + cb * X00.x, sb * X01.y + cb * X00.y);
        float2 em = make_float2(cg, -sg), ep = make_float2(cg, sg);
        Usm[l][q][0] = cmul(em, M00);
        Usm[l][q][1] = cmul(em, M01);
        Usm[l][q][2] = cmul(ep, M10);
        Usm[l][q][3] = cmul(ep, M11);
    }
    // boundaries: L_0 = |0><0|, R_16 = ones
    if (tid < 128) {
        Lsm[0][tid >> 6][tid & 63] = make_float2(tid == 0 ? 1.f : 0.f, 0.f);
    } else {
        int k = tid - 128;
        int jn = k >> 6, e = k & 63;
        Rsm[16][jn][(e >> 3) * 10 + (e & 7)] = make_float2(1.f, 0.f);
    }
    __syncthreads();

    // ---------- encoding vector folded with layer-1 gate ----------
    if (tid < 16) {
        float s = 0.f;
        #pragma unroll
        for (int k = 0; k < 16; ++k) s += pf[tid][k];
        float ang = 3.14159265358979323846f * tanhf(s + bv[tid]);
        float h = 0.5f * ang;
        float2 v0 = make_float2(cosf(h), 0.f);
        float2 v1 = make_float2(0.f, -sinf(h));
        wsm[tid][0] = cfma(Usm[0][tid][1], v1, cmul(Usm[0][tid][0], v0));
        wsm[tid][1] = cfma(Usm[0][tid][3], v1, cmul(Usm[0][tid][2], v0));
    }
    __syncthreads();

    if (tid < 128) {
        // ============ LEFT SWEEP (warps 0-3), 1 barrier/site ============
        // thread bits: 0=ap2(g0), 1=ap3(g1), 2=j, 3-4=b low, 5=b2, 6=jn
        const int t = tid;
        const int g = t & 3;
        const int j = (t >> 2) & 1;
        const int b = (t >> 3) & 7;
        const int jn = t >> 6;
        const int b3 = b >> 2, b2 = (b >> 1) & 1, b1 = b & 1;
        const int v = t & 1, u = (t >> 1) & 1, sb2 = (t >> 2) & 1;
        const int bp = t & 7;

        #pragma unroll 1
        for (int q = 0; q < 16; ++q) {
            // -- step1: T[jnj][b][ap=2g+e] = sum_a K[jnj][b][a] * L[j][a][ap]
            float2 U4v  = Usm[3][q][((jn ^ j) << 1) | b3];
            float2 P0   = cmul(U4v, Usm[2][q][(b3 << 1) | b2]);
            float2 P1   = cmul(U4v, Usm[2][q][((b3 ^ 1) << 1) | b2]);
            float2 U2x0 = Usm[1][q][(b2 << 1) | b1];
            float2 U2x1 = Usm[1][q][((b2 ^ 1) << 1) | b1];
            float2 w0 = wsm[q][b1], w1 = wsm[q][b1 ^ 1];
            float2 hw00 = cmul(U2x0, w0), hw01 = cmul(U2x0, w1);
            float2 hw10 = cmul(U2x1, w0), hw11 = cmul(U2x1, w1);
            const float4* Lr = ((const float4*)Lsm[q]) + j * 36 + g;
            float4 A0 = Lr[0],  A1 = Lr[4],  A2 = Lr[8],  A3 = Lr[12];
            float4 A4 = Lr[16], A5 = Lr[20], A6 = Lr[24], A7 = Lr[28];
            float2 n0e = cfma(hw01, f2lo(A1), cmul(hw00, f2lo(A0)));
            n0e = cfma(hw10, f2lo(A2), n0e);  n0e = cfma(hw11, f2lo(A3), n0e);
            float2 n1e = cfma(hw01, f2lo(A5), cmul(hw00, f2lo(A4)));
            n1e = cfma(hw10, f2lo(A6), n1e);  n1e = cfma(hw11, f2lo(A7), n1e);
            float2 oe = cfma(P1, n1e, cmul(P0, n0e));               // T[e=0]
            float2 n0o = cfma(hw01, f2hi(A1), cmul(hw00, f2hi(A0)));
            n0o = cfma(hw10, f2hi(A2), n0o);  n0o = cfma(hw11, f2hi(A3), n0o);
            float2 n1o = cfma(hw01, f2hi(A5), cmul(hw00, f2hi(A4)));
            n1o = cfma(hw10, f2hi(A6), n1o);  n1o = cfma(hw11, f2hi(A7), n1o);
            float2 oo = cfma(P1, n1o, cmul(P0, n0o));               // T[e=1]

            // -- A-level (in-thread, contract ap1): A[p1] = sum_e T[e]*conj(w[p1^e])
            float2 Aa = cadd(cmulc(oe, w0 = wsm[q][0]), cmulc(oo, w1 = wsm[q][1]));
            float2 Ab = cadd(cmulc(oe, w1), cmulc(oo, w0));

            // -- hop1: xor 1 (ap2 -> p1)
            float2 recvA = shflx(v ? Aa : Ab, 1);
            float2 Av = v ? Ab : Aa;
            float2 e0 = Usm[1][q][(v << 1) | v];
            float2 e1 = Usm[1][q][((v ^ 1) << 1) | v];
            float2 B0 = cadd(cmulc(Av, e0), cmulc(recvA, e1));   // p2=0
            float2 B1 = cadd(cmulc(Av, e1), cmulc(recvA, e0));   // p2=1

            // -- hop2: xor 2 (ap3 -> p2)
            float2 recvB = shflx(u ? B0 : B1, 2);
            float2 Bu = u ? B1 : B0;
            float2 f0 = Usm[2][q][(u << 1) | u];
            float2 f1 = Usm[2][q][((u ^ 1) << 1) | u];
            float2 C0 = cadd(cmulc(Bu, f0), cmulc(recvB, f1));   // p3=0
            float2 C1 = cadd(cmulc(Bu, f1), cmulc(recvB, f0));   // p3=1

            // -- hop3: xor 4 (j -> p3)
            float2 recvC = shflx(sb2 ? C0 : C1, 4);
            float2 Cs = sb2 ? C1 : C0;
            float2 q0 = Usm[3][q][((jn ^ sb2) << 1) | sb2];
            float2 q1 = Usm[3][q][((jn ^ sb2 ^ 1) << 1) | sb2];
            Lsm[q + 1][jn][b * 8 + bp] = cadd(cmulc(Cs, q0), cmulc(recvC, q1));
            BARL;
        }
    } else {
        // ============ RIGHT SWEEP (warps 4-7), 1 barrier/site ============
        // thread bits: 0=jn, 1-3=b, 4=g0(ap2), 5=g1(ap3), 6=j
        const int t = tid - 128;
        const int jn = t & 1;
        const int b  = (t >> 1) & 7;
        const int b1 = (t >> 1) & 1, b2v = (t >> 2) & 1, b3 = (t >> 3) & 1;
        const int g  = (t >> 4) & 3;
        const int j  = t >> 6;
        const int x2 = g & 1, x3 = g >> 1;
        const int sts_off = j * 80 + ((t >> 1) & 7) * 10 + ((g << 1) | (t & 1));

        #pragma unroll 1
        for (int q = 15; q >= 1; --q) {
            // -- step1: S[jnj][b][ap] = sum_bp R[jn][b][bp]*conj(K[jnj][bp][ap])
            float2 U2a = Usm[1][q][(x2 << 1) | 0], U2b = Usm[1][q][(x2 << 1) | 1];
            float2 U2c = Usm[1][q][((x2 ^ 1) << 1) | 0], U2d = Usm[1][q][((x2 ^ 1) << 1) | 1];
            float2 wA = wsm[q][0], wB = wsm[q][1];
            float2 h00 = cmul(U2a, wA), h01 = cmul(U2b, wB);
            float2 h10 = cmul(U2c, wA), h11 = cmul(U2d, wB);
            float2 g00 = cmul(U2a, wB), g01 = cmul(U2b, wA);
            float2 g10 = cmul(U2c, wB), g11 = cmul(U2d, wA);
            float2 V30 = Usm[2][q][(x3 << 1) | 0], V31 = Usm[2][q][(x3 << 1) | 1];
            float2 V32 = Usm[2][q][((x3 ^ 1) << 1) | 0], V33 = Usm[2][q][((x3 ^ 1) << 1) | 1];
            float2 U40 = Usm[3][q][((jn ^ j) << 1) | 0];
            float2 U41 = Usm[3][q][((jn ^ j) << 1) | 1];
            const float4* Rr = ((const float4*)Rsm[q + 1]) + jn * 40 + b * 5;
            float4 R0 = Rr[0], R1 = Rr[1], R2 = Rr[2], R3 = Rr[3];
            // e=0
            float2 m00 = cmulc(f2lo(R0), h00); m00.x = fmaf(f2hi(R0).x, h01.x, fmaf(f2hi(R0).y, h01.y, m00.x)); m00.y = fmaf(f2hi(R0).y, h01.x, fmaf(-f2hi(R0).x, h01.y, m00.y));
            float2 m01 = cmulc(f2lo(R1), h10); m01.x = fmaf(f2hi(R1).x, h11.x, fmaf(f2hi(R1).y, h11.y, m01.x)); m01.y = fmaf(f2hi(R1).y, h11.x, fmaf(-f2hi(R1).x, h11.y, m01.y));
            float2 m10 = cmulc(f2lo(R2), h00); m10.x = fmaf(f2hi(R2).x, h01.x, fmaf(f2hi(R2).y, h01.y, m10.x)); m10.y = fmaf(f2hi(R2).y, h01.x, fmaf(-f2hi(R2).x, h01.y, m10.y));
            float2 m11 = cmulc(f2lo(R3), h10); m11.x = fmaf(f2hi(R3).x, h11.x, fmaf(f2hi(R3).y, h11.y, m11.x)); m11.y = fmaf(f2hi(R3).y, h11.x, fmaf(-f2hi(R3).x, h11.y, m11.y));
            float2 n0 = cadd(cmulc(m00, V30), cmulc(m01, V31));
            float2 n1 = cadd(cmulc(m10, V32), cmulc(m11, V33));
            float2 oe = cadd(cmulc(n0, U40), cmulc(n1, U41));      // S[e=0]
            // e=1
            m00 = cmulc(f2lo(R0), g00); m00.x = fmaf(f2hi(R0).x, g01.x, fmaf(f2hi(R0).y, g01.y, m00.x)); m00.y = fmaf(f2hi(R0).y, g01.x, fmaf(-f2hi(R0).x, g01.y, m00.y));
            m01 = cmulc(f2lo(R1), g10); m01.x = fmaf(f2hi(R1).x, g11.x, fmaf(f2hi(R1).y, g11.y, m01.x)); m01.y = fmaf(f2hi(R1).y, g11.x, fmaf(-f2hi(R1).x, g11.y, m01.y));
            m10 = cmulc(f2lo(R2), g00); m10.x = fmaf(f2hi(R2).x, g01.x, fmaf(f2hi(R2).y, g01.y, m10.x)); m10.y = fmaf(f2hi(R2).y, g01.x, fmaf(-f2hi(R2).x, g01.y, m10.y));
            m11 = cmulc(f2lo(R3), g10); m11.x = fmaf(f2hi(R3).x, g11.x, fmaf(f2hi(R3).y, g11.y, m11.x)); m11.y = fmaf(f2hi(R3).y, g11.x, fmaf(-f2hi(R3).x, g11.y, m11.y));
            n0 = cadd(cmulc(m00, V30), cmulc(m01, V31));
            n1 = cadd(cmulc(m10, V32), cmulc(m11, V33));
            float2 oo = cadd(cmulc(n0, U40), cmulc(n1, U41));      // S[e=1]

            // -- hop1: xor 1 (jn -> e), apply U4[jn^j, b3], sum jn
            float2 recvS = shflx(jn ? oe : oo, 1);
            float2 Sv = jn ? oo : oe;
            float2 X = cadd(cmul(Usm[3][q][((jn ^ j) << 1) | b3], Sv),
                            cmul(Usm[3][q][(((jn ^ 1) ^ j) << 1) | b3], recvS));
            // -- hop2: xor 8 (b3 -> a3), U3[b3^a3, b2]
            float2 X2 = cadd(cmul(Usm[2][q][(0 << 1) | b2v], X),
                             cmul(Usm[2][q][(1 << 1) | b2v], shflx(X, 8)));
            // -- hop3: xor 4 (b2 -> a2), U2[b2^a2, b1]
            float2 X3 = cadd(cmul(Usm[1][q][(0 << 1) | b1], X2),
                             cmul(Usm[1][q][(1 << 1) | b1], shflx(X2, 4)));
            // -- hop4: xor 2 (b1 -> a1), w[b1^a1]
            float2 X4 = cadd(cmul(wsm[q][0], X3),
                             cmul(wsm[q][1], shflx(X3, 2)));
            Rsm[q][0][sts_off] = X4;
            BARR;
        }
    }

    __syncthreads();

    // ---------- Z_q = sum_jn (-1)^jn Re< L_{q+1}[jn], R_{q+1}[jn] > ----------
    {
        int q = tid >> 4, s = tid & 15;
        int jn = s >> 3, b = s & 7;
        const float4* Lr = ((const float4*)Lsm[q + 1]) + jn * 36 + b * 4;
        const float4* Rr = ((const float4*)Rsm[q + 1]) + jn * 40 + b * 5;
        float acc = 0.f;
        #pragma unroll
        for (int c = 0; c < 4; ++c) {
            float4 l = Lr[c], r = Rr[c];
            acc += l.x * r.x - l.y * r.y + l.z * r.z - l.w * r.w;
        }
        if (jn) acc = -acc;
        #pragma unroll
        for (int o = 8; o; o >>= 1)
            acc += __shfl_xor_sync(0xffffffffu, acc, o);
        if (s == 0) out[(size_t)bat * 16 + q] = acc;
    }
}

extern "C" void kernel_launch(void* const* d_in, const int* in_sizes, int n_in,
                              void* d_out, int out_size) {
    const float* ctx = nullptr;
    const float* Wm  = nullptr;
    const float* bv  = nullptr;
    const float* prm = nullptr;
    for (int i = 0; i < n_in; ++i) {
        int sz = in_sizes[i];
        const float* p = (const float*)d_in[i];
        if (sz == 16)        bv  = p;
        else if (sz == 192)  prm = p;
        else if (sz == 4096) Wm  = p;
        else                 ctx = p;  // B*256
    }
    if (!ctx) ctx = (const float*)d_in[0];
    if (!Wm)  Wm  = (const float*)d_in[1];
    if (!bv)  bv  = (const float*)d_in[2];
    if (!prm) prm = (const float*)d_in[3];

    float* out = (float*)d_out;
    int B = out_size / 16;
    if (B <= 0) return;
    pqc_mps_kernel<<<B, 256>>>(ctx, Wm, bv, prm, out);
}

// round 11
// speedup vs baseline: 1.9252x; 1.0023x over previous
#include <cuda_runtime.h>
#include <cuda_bf16.h>
#include <cstddef>

// ============================================================================
// MiniQuixerPQCBlock — exact MPS (bond dim 16) contraction.
// Warp-specialized sweeps + shfl butterfly reduce-scatter (R9), with the hot
// inner contractions rewritten as packed f32x2 FMA (FFMA2) via inline PTX
// in P/Q split form (ptxas never emits FFMA2 from C++).
// ============================================================================

typedef unsigned long long u64;

__device__ __forceinline__ u64 pk2(float lo, float hi) {
    u64 r; asm("mov.b64 %0, {%1, %2};" : "=l"(r) : "f"(lo), "f"(hi)); return r;
}
__device__ __forceinline__ u64 spl(float v) { return pk2(v, v); }
__device__ __forceinline__ float2 up2(u64 v) {
    float2 r; asm("mov.b64 {%0, %1}, %2;" : "=f"(r.x), "=f"(r.y) : "l"(v)); return r;
}
__device__ __forceinline__ u64 ffma2(u64 a, u64 b, u64 c) {
    u64 r; asm("fma.rn.f32x2 %0, %1, %2, %3;" : "=l"(r) : "l"(a), "l"(b), "l"(c)); return r;
}
__device__ __forceinline__ u64 fmul2(u64 a, u64 b) {
    u64 r; asm("mul.rn.f32x2 %0, %1, %2;" : "=l"(r) : "l"(a), "l"(b)); return r;
}
// plain-gate combine: result = {P.lo - Q.hi, P.hi + Q.lo}
__device__ __forceinline__ float2 comb(u64 P, u64 Q) {
    float2 p = up2(P), q = up2(Q);
    return make_float2(p.x - q.y, p.y + q.x);
}
// conj-gate combine: result = {P.lo + Q.hi, P.hi - Q.lo}
__device__ __forceinline__ float2 combc(u64 P, u64 Q) {
    float2 p = up2(P), q = up2(Q);
    return make_float2(p.x + q.y, p.y - q.x);
}

__device__ __forceinline__ float2 cmul(float2 a, float2 b) {
    return make_float2(fmaf(a.x, b.x, -a.y * b.y), fmaf(a.x, b.y, a.y * b.x));
}
__device__ __forceinline__ float2 cfma(float2 a, float2 b, float2 c) {
    c.x = fmaf(a.x, b.x, fmaf(-a.y, b.y, c.x));
    c.y = fmaf(a.x, b.y, fmaf(a.y, b.x, c.y));
    return c;
}
__device__ __forceinline__ float2 cmulc(float2 a, float2 b) {  // a*conj(b)
    return make_float2(fmaf(a.x, b.x, a.y * b.y), fmaf(a.y, b.x, -a.x * b.y));
}
__device__ __forceinline__ float2 cadd(float2 a, float2 b) {
    return make_float2(a.x + b.x, a.y + b.y);
}
__device__ __forceinline__ float2 shflx(float2 v, int m) {
    v.x = __shfl_xor_sync(0xffffffffu, v.x, m);
    v.y = __shfl_xor_sync(0xffffffffu, v.y, m);
    return v;
}

#define BARL asm volatile("bar.sync 1, 128;" ::: "memory")
#define BARR asm volatile("bar.sync 2, 128;" ::: "memory")

__global__ __launch_bounds__(256) void pqc_mps_kernel(
    const float* __restrict__ ctx,   // [B, 256]
    const float* __restrict__ Wm,    // [16, 256]
    const float* __restrict__ bv,    // [16]
    const float* __restrict__ prm,   // [4, 16, 3]
    float* __restrict__ out)         // [B, 16]
{
    __shared__ __align__(16) float2 Lsm[17][2][72];
    __shared__ __align__(16) float2 Rsm[17][2][80];
    __shared__ float2 Usm[4][16][4];   // fused gates [layer][wire][r*2+c]
    __shared__ float2 wsm[16][2];      // U1 * RX(angle)|0>
    __shared__ float  pf[16][16];

    const int tid = threadIdx.x;
    const int bat = blockIdx.x;

    // ---------- encoding angle partial dots ----------
    {
        int q = tid >> 4, s = tid & 15;
        const float* cr = ctx + (size_t)bat * 256;
        const float* wr = Wm + (size_t)q * 256;
        float acc = 0.f;
        #pragma unroll
        for (int k = 0; k < 16; ++k) acc = fmaf(cr[s + 16 * k], wr[s + 16 * k], acc);
        pf[q][s] = acc;
    }
    // ---------- fused variational gates U = RZ*RY*RX ----------
    if (tid < 64) {
        int l = tid >> 4, q = tid & 15;
        const float* p = prm + (size_t)(l * 16 + q) * 3;
        float ca = cosf(0.5f * p[0]), sa = sinf(0.5f * p[0]);
        float cb = cosf(0.5f * p[1]), sb = sinf(0.5f * p[1]);
        float cg = cosf(0.5f * p[2]), sg = sinf(0.5f * p[2]);
        float2 X00 = make_float2(ca, 0.f), X01 = make_float2(0.f, -sa);
        float2 M00 = make_float2(cb * X00.x - sb * X01.x, cb * X00.y - sb * X01.y);
        float2 M01 = make_float2(cb * X01.x - sb * X00.x, cb * X01.y - sb * X00.y);
        float2 M10 = make_float2(sb * X00.x + cb * X01.x, sb * X00.y + cb * X01.y);
        float2 M11 = make_float2(sb * X01.x + cb * X00.x, sb * X01.y + cb * X00.y);
        float2 em = make_float2(cg, -sg), ep = make_float2(cg, sg);
        Usm[l][q][0] = cmul(em, M00);
        Usm[l][q][1] = cmul(em, M01);
        Usm[l][q][2] = cmul(ep, M10);
        Usm[l][q][3] = cmul(ep, M11);
    }
    // boundaries: L_0 = |0><0|, R_16 = ones
    if (tid < 128) {
        Lsm[0][tid >> 6][tid & 63] = make_float2(tid == 0 ? 1.f : 0.f, 0.f);
    } else {
        int k = tid - 128;
        int jn = k >> 6, e = k & 63;
        Rsm[16][jn][(e >> 3) * 10 + (e & 7)] = make_float2(1.f, 0.f);
    }
    __syncthreads();

    // ---------- encoding vector folded with layer-1 gate ----------
    if (tid < 16) {
        float s = 0.f;
        #pragma unroll
        for (int k = 0; k < 16; ++k) s += pf[tid][k];
        float ang = 3.14159265358979323846f * tanhf(s + bv[tid]);
        float h = 0.5f * ang;
        float2 v0 = make_float2(cosf(h), 0.f);
        float2 v1 = make_float2(0.f, -sinf(h));
        wsm[tid][0] = cfma(Usm[0][tid][1], v1, cmul(Usm[0][tid][0], v0));
        wsm[tid][1] = cfma(Usm[0][tid][3], v1, cmul(Usm[0][tid][2], v0));
    }
    __syncthreads();

    if (tid < 128) {
        // ============ LEFT SWEEP (warps 0-3), 1 barrier/site ============
        const int t = tid;
        const int g = t & 3;
        const int j = (t >> 2) & 1;
        const int b = (t >> 3) & 7;
        const int jn = t >> 6;
        const int b3 = b >> 2, b2 = (b >> 1) & 1, b1 = b & 1;
        const int v = t & 1, u = (t >> 1) & 1, sb2 = (t >> 2) & 1;
        const int bp = t & 7;

        #pragma unroll 1
        for (int q = 0; q < 16; ++q) {
            // gates
            float2 U4v  = Usm[3][q][((jn ^ j) << 1) | b3];
            float2 P0   = cmul(U4v, Usm[2][q][(b3 << 1) | b2]);
            float2 P1   = cmul(U4v, Usm[2][q][((b3 ^ 1) << 1) | b2]);
            float2 wA = wsm[q][0], wB = wsm[q][1];
            float2 w0 = b1 ? wB : wA, w1 = b1 ? wA : wB;
            float2 U2x0 = Usm[1][q][(b2 << 1) | b1];
            float2 U2x1 = Usm[1][q][((b2 ^ 1) << 1) | b1];
            float2 hw00 = cmul(U2x0, w0), hw01 = cmul(U2x0, w1);
            float2 hw10 = cmul(U2x1, w0), hw11 = cmul(U2x1, w1);
            u64 hx0 = spl(hw00.x), hy0 = spl(hw00.y);
            u64 hx1 = spl(hw01.x), hy1 = spl(hw01.y);
            u64 hx2 = spl(hw10.x), hy2 = spl(hw10.y);
            u64 hx3 = spl(hw11.x), hy3 = spl(hw11.y);

            // step1 inner contraction via packed FFMA2 (P/Q split form)
            const ulonglong2* Lr = ((const ulonglong2*)Lsm[q]) + j * 36 + g;
            ulonglong2 A0 = Lr[0],  A1 = Lr[4],  A2 = Lr[8],  A3 = Lr[12];
            u64 P0e = fmul2(hx0, A0.x); P0e = ffma2(hx1, A1.x, P0e);
            P0e = ffma2(hx2, A2.x, P0e); P0e = ffma2(hx3, A3.x, P0e);
            u64 Q0e = fmul2(hy0, A0.x); Q0e = ffma2(hy1, A1.x, Q0e);
            Q0e = ffma2(hy2, A2.x, Q0e); Q0e = ffma2(hy3, A3.x, Q0e);
            u64 P0o = fmul2(hx0, A0.y); P0o = ffma2(hx1, A1.y, P0o);
            P0o = ffma2(hx2, A2.y, P0o); P0o = ffma2(hx3, A3.y, P0o);
            u64 Q0o = fmul2(hy0, A0.y); Q0o = ffma2(hy1, A1.y, Q0o);
            Q0o = ffma2(hy2, A2.y, Q0o); Q0o = ffma2(hy3, A3.y, Q0o);
            ulonglong2 A4 = Lr[16], A5 = Lr[20], A6 = Lr[24], A7 = Lr[28];
            u64 P1e = fmul2(hx0, A4.x); P1e = ffma2(hx1, A5.x, P1e);
            P1e = ffma2(hx2, A6.x, P1e); P1e = ffma2(hx3, A7.x, P1e);
            u64 Q1e = fmul2(hy0, A4.x); Q1e = ffma2(hy1, A5.x, Q1e);
            Q1e = ffma2(hy2, A6.x, Q1e); Q1e = ffma2(hy3, A7.x, Q1e);
            u64 P1o = fmul2(hx0, A4.y); P1o = ffma2(hx1, A5.y, P1o);
            P1o = ffma2(hx2, A6.y, P1o); P1o = ffma2(hx3, A7.y, P1o);
            u64 Q1o = fmul2(hy0, A4.y); Q1o = ffma2(hy1, A5.y, Q1o);
            Q1o = ffma2(hy2, A6.y, Q1o); Q1o = ffma2(hy3, A7.y, Q1o);
            float2 n0e = comb(P0e, Q0e), n1e = comb(P1e, Q1e);
            float2 n0o = comb(P0o, Q0o), n1o = comb(P1o, Q1o);
            float2 oe = cfma(P1, n1e, cmul(P0, n0e));   // T[e=0]
            float2 oo = cfma(P1, n1o, cmul(P0, n0o));   // T[e=1]

            // A-level: contract ap1 with conj(w)
            float2 Aa = cadd(cmulc(oe, wA), cmulc(oo, wB));
            float2 Ab = cadd(cmulc(oe, wB), cmulc(oo, wA));

            // hop1: xor 1 (ap2 -> p1)
            float2 recvA = shflx(v ? Aa : Ab, 1);
            float2 Av = v ? Ab : Aa;
            float2 e0 = Usm[1][q][(v << 1) | v];
            float2 e1 = Usm[1][q][((v ^ 1) << 1) | v];
            float2 B0 = cadd(cmulc(Av, e0), cmulc(recvA, e1));
            float2 B1 = cadd(cmulc(Av, e1), cmulc(recvA, e0));
            // hop2: xor 2 (ap3 -> p2)
            float2 recvB = shflx(u ? B0 : B1, 2);
            float2 Bu = u ? B1 : B0;
            float2 f0 = Usm[2][q][(u << 1) | u];
            float2 f1 = Usm[2][q][((u ^ 1) << 1) | u];
            float2 C0 = cadd(cmulc(Bu, f0), cmulc(recvB, f1));
            float2 C1 = cadd(cmulc(Bu, f1), cmulc(recvB, f0));
            // hop3: xor 4 (j -> p3)
            float2 recvC = shflx(sb2 ? C0 : C1, 4);
            float2 Cs = sb2 ? C1 : C0;
            float2 q0 = Usm[3][q][((jn ^ sb2) << 1) | sb2];
            float2 q1 = Usm[3][q][((jn ^ sb2 ^ 1) << 1) | sb2];
            Lsm[q + 1][jn][b * 8 + bp] = cadd(cmulc(Cs, q0), cmulc(recvC, q1));
            BARL;
        }
    } else {
        // ============ RIGHT SWEEP (warps 4-7), 1 barrier/site ============
        const int t = tid - 128;
        const int jn = t & 1;
        const int b  = (t >> 1) & 7;
        const int b1 = (t >> 1) & 1, b2v = (t >> 2) & 1, b3 = (t >> 3) & 1;
        const int g  = (t >> 4) & 3;
        const int j  = t >> 6;
        const int x2 = g & 1, x3 = g >> 1;
        const int sts_off = j * 80 + b * 10 + ((g << 1) | jn);

        #pragma unroll 1
        for (int q = 15; q >= 1; --q) {
            float2 wA = wsm[q][0], wB = wsm[q][1];
            float2 U2a = Usm[1][q][(x2 << 1) | 0], U2b = Usm[1][q][(x2 << 1) | 1];
            float2 U2c = Usm[1][q][((x2 ^ 1) << 1) | 0], U2d = Usm[1][q][((x2 ^ 1) << 1) | 1];
            float2 V30 = Usm[2][q][(x3 << 1) | 0], V31 = Usm[2][q][(x3 << 1) | 1];
            float2 V32 = Usm[2][q][((x3 ^ 1) << 1) | 0], V33 = Usm[2][q][((x3 ^ 1) << 1) | 1];
            float2 U40 = Usm[3][q][((jn ^ j) << 1) | 0];
            float2 U41 = Usm[3][q][((jn ^ j) << 1) | 1];

            const ulonglong2* Rr = ((const ulonglong2*)Rsm[q + 1]) + jn * 40 + b * 5;
            ulonglong2 R0 = Rr[0], R1 = Rr[1], R2 = Rr[2], R3 = Rr[3];

            float2 oe, oo;
            {   // e = 0: gates h = U2 * w (ap1=0 pattern)
                float2 h00 = cmul(U2a, wA), h01 = cmul(U2b, wB);
                float2 h10 = cmul(U2c, wA), h11 = cmul(U2d, wB);
                u64 ax0 = spl(h00.x), ay0 = spl(h00.y);
                u64 ax1 = spl(h01.x), ay1 = spl(h01.y);
                u64 ax2 = spl(h10.x), ay2 = spl(h10.y);
                u64 ax3 = spl(h11.x), ay3 = spl(h11.y);
                u64 Pm, Qm;
                Pm = ffma2(ax1, R0.y, fmul2(ax0, R0.x));
                Qm = ffma2(ay1, R0.y, fmul2(ay0, R0.x));
                float2 m00 = combc(Pm, Qm);
                Pm = ffma2(ax3, R1.y, fmul2(ax2, R1.x));
                Qm = ffma2(ay3, R1.y, fmul2(ay2, R1.x));
                float2 m01 = combc(Pm, Qm);
                Pm = ffma2(ax1, R2.y, fmul2(ax0, R2.x));
                Qm = ffma2(ay1, R2.y, fmul2(ay0, R2.x));
                float2 m10 = combc(Pm, Qm);
                Pm = ffma2(ax3, R3.y, fmul2(ax2, R3.x));
                Qm = ffma2(ay3, R3.y, fmul2(ay2, R3.x));
                float2 m11 = combc(Pm, Qm);
                float2 n0 = cadd(cmulc(m00, V30), cmulc(m01, V31));
                float2 n1 = cadd(cmulc(m10, V32), cmulc(m11, V33));
                oe = cadd(cmulc(n0, U40), cmulc(n1, U41));
            }
            {   // e = 1: gates g = U2 * w-swapped
                float2 g00 = cmul(U2a, wB), g01 = cmul(U2b, wA);
                float2 g10 = cmul(U2c, wB), g11 = cmul(U2d, wA);
                u64 ax0 = spl(g00.x), ay0 = spl(g00.y);
                u64 ax1 = spl(g01.x), ay1 = spl(g01.y);
                u64 ax2 = spl(g10.x), ay2 = spl(g10.y);
                u64 ax3 = spl(g11.x), ay3 = spl(g11.y);
                u64 Pm, Qm;
                Pm = ffma2(ax1, R0.y, fmul2(ax0, R0.x));
                Qm = ffma2(ay1, R0.y, fmul2(ay0, R0.x));
                float2 m00 = combc(Pm, Qm);
                Pm = ffma2(ax3, R1.y, fmul2(ax2, R1.x));
                Qm = ffma2(ay3, R1.y, fmul2(ay2, R1.x));
                float2 m01 = combc(Pm, Qm);
                Pm = ffma2(ax1, R2.y, fmul2(ax0, R2.x));
                Qm = ffma2(ay1, R2.y, fmul2(ay0, R2.x));
                float2 m10 = combc(Pm, Qm);
                Pm = ffma2(ax3, R3.y, fmul2(ax2, R3.x));
                Qm = ffma2(ay3, R3.y, fmul2(ay2, R3.x));
                float2 m11 = combc(Pm, Qm);
                float2 n0 = cadd(cmulc(m00, V30), cmulc(m01, V31));
                float2 n1 = cadd(cmulc(m10, V32), cmulc(m11, V33));
                oo = cadd(cmulc(n0, U40), cmulc(n1, U41));
            }

            // hop1: xor 1 (jn -> e), apply U4[jn^j, b3], sum jn
            float2 recvS = shflx(jn ? oe : oo, 1);
            float2 Sv = jn ? oo : oe;
            float2 X = cadd(cmul(Usm[3][q][((jn ^ j) << 1) | b3], Sv),
                            cmul(Usm[3][q][(((jn ^ 1) ^ j) << 1) | b3], recvS));
            // hop2: xor 8 (b3 -> a3)
            float2 X2 = cadd(cmul(Usm[2][q][(0 << 1) | b2v], X),
                             cmul(Usm[2][q][(1 << 1) | b2v], shflx(X, 8)));
            // hop3: xor 4 (b2 -> a2)
            float2 X3 = cadd(cmul(Usm[1][q][(0 << 1) | b1], X2),
                             cmul(Usm[1][q][(1 << 1) | b1], shflx(X2, 4)));
            // hop4: xor 2 (b1 -> a1)
            float2 X4 = cadd(cmul(wA, X3), cmul(wB, shflx(X3, 2)));
            Rsm[q][0][sts_off] = X4;
            BARR;
        }
    }

    __syncthreads();

    // ---------- Z_q = sum_jn (-1)^jn Re< L_{q+1}[jn], R_{q+1}[jn] > ----------
    {
        int q = tid >> 4, s = tid & 15;
        int jn = s >> 3, b = s & 7;
        const float4* Lr = ((const float4*)Lsm[q + 1]) + jn * 36 + b * 4;
        const float4* Rr = ((const float4*)Rsm[q + 1]) + jn * 40 + b * 5;
        float acc = 0.f;
        #pragma unroll
        for (int c = 0; c < 4; ++c) {
            float4 l = Lr[c], r = Rr[c];
            acc += l.x * r.x - l.y * r.y + l.z * r.z - l.w * r.w;
        }
        if (jn) acc = -acc;
        #pragma unroll
        for (int o = 8; o; o >>= 1)
            acc += __shfl_xor_sync(0xffffffffu, acc, o);
        if (s == 0) out[(size_t)bat * 16 + q] = acc;
    }
}

extern "C" void kernel_launch(void* const* d_in, const int* in_sizes, int n_in,
                              void* d_out, int out_size) {
    const float* ctx = nullptr;
    const float* Wm  = nullptr;
    const float* bv  = nullptr;
    const float* prm = nullptr;
    for (int i = 0; i < n_in; ++i) {
        int sz = in_sizes[i];
        const float* p = (const float*)d_in[i];
        if (sz == 16)        bv  = p;
        else if (sz == 192)  prm = p;
        else if (sz == 4096) Wm  = p;
        else                 ctx = p;  // B*256
    }
    if (!ctx) ctx = (const float*)d_in[0];
    if (!Wm)  Wm  = (const float*)d_in[1];
    if (!bv)  bv  = (const float*)d_in[2];
    if (!prm) prm = (const float*)d_in[3];

    float* out = (float*)d_out;
    int B = out_size / 16;
    if (B <= 0) return;
    pqc_mps_kernel<<<B, 256>>>(ctx, Wm, bv, prm, out);
}

// round 12
// speedup vs baseline: 2.7467x; 1.4267x over previous
#include <cuda_runtime.h>
#include <cuda_bf16.h>
#include <cstddef>

// ============================================================================
// MiniQuixerPQCBlock — exact MPS (bond dim 16) contraction, fully warp-level.
// Environment (2 x 8 x 8 = 128 complex) lives in ONE warp's registers:
//   in-thread bits: r0 = ket low bit (z1), r1 = bra low bit (zp1)
//   lane bits:      0=z2, 1=zp2, 2=z3, 3=zp3, 4=j (shared layer-4 carry)
// Site transfer = 7 elementary XOR-gate passes (2 in-thread + 5 shfl_xor),
// 2 cmul per entry per pass. No block barriers, no smem env reads in sweeps.
// Warp 0 = left sweep, warp 1 = right sweep; Z in a final 64-thread phase.
// ============================================================================

__device__ __forceinline__ float2 cmul(float2 a, float2 b) {
    return make_float2(fmaf(a.x, b.x, -a.y * b.y), fmaf(a.x, b.y, a.y * b.x));
}
__device__ __forceinline__ float2 cfma(float2 a, float2 b, float2 c) {      // c += a*b
    c.x = fmaf(a.x, b.x, fmaf(-a.y, b.y, c.x));
    c.y = fmaf(a.x, b.y, fmaf(a.y, b.x, c.y));
    return c;
}
__device__ __forceinline__ float2 cmulc(float2 a, float2 b) {               // a*conj(b)
    return make_float2(fmaf(a.x, b.x, a.y * b.y), fmaf(a.y, b.x, -a.x * b.y));
}
__device__ __forceinline__ float2 cfmac(float2 a, float2 b, float2 c) {     // c += a*conj(b)
    c.x = fmaf(a.x, b.x, fmaf(a.y, b.y, c.x));
    c.y = fmaf(a.y, b.x, fmaf(-a.x, b.y, c.y));
    return c;
}
__device__ __forceinline__ float2 shflx(float2 v, int m) {
    v.x = __shfl_xor_sync(0xffffffffu, v.x, m);
    v.y = __shfl_xor_sync(0xffffffffu, v.y, m);
    return v;
}

struct Env { float2 e00, e01, e10, e11; };  // e[r1][r0]

__device__ __forceinline__ Env shfl_env(const Env& E, int m) {
    Env P;
    P.e00 = shflx(E.e00, m); P.e01 = shflx(E.e01, m);
    P.e10 = shflx(E.e10, m); P.e11 = shflx(E.e11, m);
    return P;
}

// in-thread XOR pass over r0: out[B] = g[B]*in[0] + g[B^1]*in[1]
__device__ __forceinline__ void pass_w_ket(Env& E, float2 w0, float2 w1) {
    float2 n00 = cfma(w1, E.e01, cmul(w0, E.e00));
    float2 n01 = cfma(w0, E.e01, cmul(w1, E.e00));
    float2 n10 = cfma(w1, E.e11, cmul(w0, E.e10));
    float2 n11 = cfma(w0, E.e11, cmul(w1, E.e10));
    E.e00 = n00; E.e01 = n01; E.e10 = n10; E.e11 = n11;
}
// in-thread conj pass over r1
__device__ __forceinline__ void pass_w_bra(Env& E, float2 w0, float2 w1) {
    float2 n00 = cfmac(E.e10, w1, cmulc(E.e00, w0));
    float2 n10 = cfmac(E.e10, w0, cmulc(E.e00, w1));
    float2 n01 = cfmac(E.e11, w1, cmulc(E.e01, w0));
    float2 n11 = cfmac(E.e11, w0, cmulc(E.e01, w1));
    E.e00 = n00; E.e01 = n01; E.e10 = n10; E.e11 = n11;
}
// lane pass, plain gates, gate pair selected per r0 column (U2 ket)
__device__ __forceinline__ void pass_lane_ket_r0(Env& E, int m,
        float2 a0, float2 b0, float2 a1, float2 b1) {
    Env P = shfl_env(E, m);
    E.e00 = cfma(b0, P.e00, cmul(a0, E.e00));
    E.e10 = cfma(b0, P.e10, cmul(a0, E.e10));
    E.e01 = cfma(b1, P.e01, cmul(a1, E.e01));
    E.e11 = cfma(b1, P.e11, cmul(a1, E.e11));
}
// lane pass, conj gates, gate pair per r1 row (U2 bra)
__device__ __forceinline__ void pass_lane_bra_r1(Env& E, int m,
        float2 a0, float2 b0, float2 a1, float2 b1) {
    Env P = shfl_env(E, m);
    E.e00 = cfmac(P.e00, b0, cmulc(E.e00, a0));
    E.e01 = cfmac(P.e01, b0, cmulc(E.e01, a0));
    E.e10 = cfmac(P.e10, b1, cmulc(E.e10, a1));
    E.e11 = cfmac(P.e11, b1, cmulc(E.e11, a1));
}
// lane pass, plain uniform gates (U3 ket, U4 joint)
__device__ __forceinline__ void pass_lane_ket_uni(Env& E, int m, float2 gA, float2 gB) {
    Env P = shfl_env(E, m);
    E.e00 = cfma(gB, P.e00, cmul(gA, E.e00));
    E.e01 = cfma(gB, P.e01, cmul(gA, E.e01));
    E.e10 = cfma(gB, P.e10, cmul(gA, E.e10));
    E.e11 = cfma(gB, P.e11, cmul(gA, E.e11));
}
// lane pass, conj uniform gates (U3 bra)
__device__ __forceinline__ void pass_lane_bra_uni(Env& E, int m, float2 gA, float2 gB) {
    Env P = shfl_env(E, m);
    E.e00 = cfmac(P.e00, gB, cmulc(E.e00, gA));
    E.e01 = cfmac(P.e01, gB, cmulc(E.e01, gA));
    E.e10 = cfmac(P.e10, gB, cmulc(E.e10, gA));
    E.e11 = cfmac(P.e11, gB, cmulc(E.e11, gA));
}

__global__ __launch_bounds__(64) void pqc_mps_kernel(
    const float* __restrict__ ctx,   // [B, 256]
    const float* __restrict__ Wm,    // [16, 256]
    const float* __restrict__ bv,    // [16]
    const float* __restrict__ prm,   // [4, 16, 3]
    float* __restrict__ out)         // [B, 16]
{
    __shared__ __align__(16) float4 Lsm[17][2][32];  // L_{q}, q=1..16: [q][r1][lane]
    __shared__ __align__(16) float4 Rsm[17][2][32];  // R_{q}, q=1..16
    __shared__ float2 Usm[4][16][4];                 // fused gates [layer][wire][d*2+c]
    __shared__ float2 wsm[16][2];                    // U1 * RX(angle)|0>
    __shared__ float  pf[16];

    const int tid  = threadIdx.x;
    const int lane = tid & 31;
    const int warp = tid >> 5;
    const int bat  = blockIdx.x;

    // ---------- setup: encoding dots + fused gates ----------
    {
        int q = tid >> 2, quarter = tid & 3;
        const float4* cr = (const float4*)(ctx + (size_t)bat * 256) + quarter * 16;
        const float4* wr = (const float4*)(Wm + (size_t)q * 256) + quarter * 16;
        float acc = 0.f;
        #pragma unroll
        for (int k = 0; k < 16; ++k) {
            float4 c = cr[k], w = wr[k];
            acc = fmaf(c.x, w.x, acc); acc = fmaf(c.y, w.y, acc);
            acc = fmaf(c.z, w.z, acc); acc = fmaf(c.w, w.w, acc);
        }
        acc += __shfl_xor_sync(0xffffffffu, acc, 1);
        acc += __shfl_xor_sync(0xffffffffu, acc, 2);
        if (quarter == 0) pf[q] = acc;
    }
    {
        int l = tid >> 4, q = tid & 15;
        const float* p = prm + (size_t)(l * 16 + q) * 3;
        float ca = cosf(0.5f * p[0]), sa = sinf(0.5f * p[0]);
        float cb = cosf(0.5f * p[1]), sb = sinf(0.5f * p[1]);
        float cg = cosf(0.5f * p[2]), sg = sinf(0.5f * p[2]);
        float2 X00 = make_float2(ca, 0.f), X01 = make_float2(0.f, -sa);
        float2 M00 = make_float2(cb * X00.x - sb * X01.x, cb * X00.y - sb * X01.y);
        float2 M01 = make_float2(cb * X01.x - sb * X00.x, cb * X01.y - sb * X00.y);
        float2 M10 = make_float2(sb * X00.x + cb * X01.x, sb * X00.y + cb * X01.y);
        float2 M11 = make_float2(sb * X01.x + cb * X00.x, sb * X01.y + cb * X00.y);
        float2 em = make_float2(cg, -sg), ep = make_float2(cg, sg);
        Usm[l][q][0] = cmul(em, M00);
        Usm[l][q][1] = cmul(em, M01);
        Usm[l][q][2] = cmul(ep, M10);
        Usm[l][q][3] = cmul(ep, M11);
    }
    __syncthreads();
    if (tid < 16) {
        float ang = 3.14159265358979323846f * tanhf(pf[tid] + bv[tid]);
        float h = 0.5f * ang;
        float2 v0 = make_float2(cosf(h), 0.f);
        float2 v1 = make_float2(0.f, -sinf(h));
        wsm[tid][0] = cfma(Usm[0][tid][1], v1, cmul(Usm[0][tid][0], v0));
        wsm[tid][1] = cfma(Usm[0][tid][3], v1, cmul(Usm[0][tid][2], v0));
    }
    __syncthreads();

    const int l0 = lane & 1, l1 = (lane >> 1) & 1;
    const int l2 = (lane >> 2) & 1, l3 = (lane >> 3) & 1;

    if (warp == 0) {
        // =============== LEFT SWEEP: L_0 -> L_16 (registers) ===============
        Env E;
        float2 z = make_float2(0.f, 0.f);
        E.e00 = make_float2(lane == 0 ? 1.f : 0.f, 0.f);
        E.e01 = z; E.e10 = z; E.e11 = z;

        #pragma unroll 1
        for (int q = 0; q < 16; ++q) {
            float2 w0 = wsm[q][0], w1 = wsm[q][1];
            const float2* U2 = Usm[1][q];
            const float2* U3 = Usm[2][q];
            const float2* U4 = Usm[3][q];
            pass_w_ket(E, w0, w1);                                   // z1 -> b1
            pass_w_bra(E, w0, w1);                                   // zp1 -> bp1
            pass_lane_ket_r0(E, 1, U2[0], U2[2], U2[1], U2[3]);      // z2 -> b2
            pass_lane_bra_r1(E, 2, U2[0], U2[2], U2[1], U2[3]);      // zp2 -> bp2
            pass_lane_ket_uni(E, 4, U3[l0], U3[2 | l0]);             // z3 -> b3
            pass_lane_bra_uni(E, 8, U3[l1], U3[2 | l1]);             // zp3 -> bp3
            float2 G0 = cmulc(U4[l2], U4[l3]);                       // j -> jn
            float2 G1 = cmulc(U4[2 | l2], U4[2 | l3]);
            pass_lane_ket_uni(E, 16, G0, G1);
            Lsm[q + 1][0][lane] = make_float4(E.e00.x, E.e00.y, E.e01.x, E.e01.y);
            Lsm[q + 1][1][lane] = make_float4(E.e10.x, E.e10.y, E.e11.x, E.e11.y);
        }
    } else {
        // =============== RIGHT SWEEP: R_16 -> R_1 (registers) ===============
        Env E;
        float2 one = make_float2(1.f, 0.f);
        E.e00 = one; E.e01 = one; E.e10 = one; E.e11 = one;
        Rsm[16][0][lane] = make_float4(1.f, 0.f, 1.f, 0.f);
        Rsm[16][1][lane] = make_float4(1.f, 0.f, 1.f, 0.f);

        #pragma unroll 1
        for (int q = 15; q >= 1; --q) {
            float2 w0 = wsm[q][0], w1 = wsm[q][1];
            const float2* U2 = Usm[1][q];
            const float2* U3 = Usm[2][q];
            const float2* U4 = Usm[3][q];
            float2 G0 = cmulc(U4[l2], U4[l3]);                       // jn -> j
            float2 G1 = cmulc(U4[2 | l2], U4[2 | l3]);
            pass_lane_ket_uni(E, 16, G0, G1);
            pass_lane_ket_uni(E, 4, U3[l0], U3[2 | l0]);             // b3 -> a3
            pass_lane_bra_uni(E, 8, U3[l1], U3[2 | l1]);             // bp3 -> ap3
            pass_lane_ket_r0(E, 1, U2[0], U2[2], U2[1], U2[3]);      // b2 -> a2
            pass_lane_bra_r1(E, 2, U2[0], U2[2], U2[1], U2[3]);      // bp2 -> ap2
            pass_w_ket(E, w0, w1);                                   // b1 -> a1
            pass_w_bra(E, w0, w1);                                   // bp1 -> ap1
            Rsm[q][0][lane] = make_float4(E.e00.x, E.e00.y, E.e01.x, E.e01.y);
            Rsm[q][1][lane] = make_float4(E.e10.x, E.e10.y, E.e11.x, E.e11.y);
        }
    }

    __syncthreads();

    // ---------- Z_q = sum over env (sign = (-1)^{lane bit 4}) ----------
    {
        int qz = tid >> 2, part = tid & 3;
        float acc = 0.f;
        #pragma unroll
        for (int i = 0; i < 8; ++i) {
            int ln = part * 8 + i;
            float4 la = Lsm[qz + 1][0][ln], ra = Rsm[qz + 1][0][ln];
            float4 lb = Lsm[qz + 1][1][ln], rb = Rsm[qz + 1][1][ln];
            float s = la.x * ra.x - la.y * ra.y + la.z * ra.z - la.w * ra.w
                    + lb.x * rb.x - lb.y * rb.y + lb.z * rb.z - lb.w * rb.w;
            acc += (ln & 16) ? -s : s;
        }
        acc += __shfl_xor_sync(0xffffffffu, acc, 1);
        acc += __shfl_xor_sync(0xffffffffu, acc, 2);
        if (part == 0) out[(size_t)bat * 16 + qz] = acc;
    }
}

extern "C" void kernel_launch(void* const* d_in, const int* in_sizes, int n_in,
                              void* d_out, int out_size) {
    const float* ctx = nullptr;
    const float* Wm  = nullptr;
    const float* bv  = nullptr;
    const float* prm = nullptr;
    for (int i = 0; i < n_in; ++i) {
        int sz = in_sizes[i];
        const float* p = (const float*)d_in[i];
        if (sz == 16)        bv  = p;
        else if (sz == 192)  prm = p;
        else if (sz == 4096) Wm  = p;
        else                 ctx = p;  // B*256
    }
    if (!ctx) ctx = (const float*)d_in[0];
    if (!Wm)  Wm  = (const float*)d_in[1];
    if (!bv)  bv  = (const float*)d_in[2];
    if (!prm) prm = (const float*)d_in[3];

    float* out = (float*)d_out;
    int B = out_size / 16;
    if (B <= 0) return;
    pqc_mps_kernel<<<B, 64>>>(ctx, Wm, bv, prm, out);
}